// round 5
// baseline (speedup 1.0000x reference)
#include <cuda_runtime.h>
#include <cstdint>

#define N_NODES 40000
#define N_EDGES 400000
#define H2f 0.01f
#define LN_EPS 1e-5f

// ---------------- device scratch (allocation-free rule: __device__ globals) ----
__device__ float g_xn[N_NODES * 64];
__device__ float g_xn_old[N_NODES * 64];
__device__ float g_tmp_n[N_NODES * 64];
__device__ float g_si[N_NODES * 64];
__device__ float g_sj[N_NODES * 64];
__device__ float g_xe[N_EDGES * 64];
__device__ float g_xe_old[N_EDGES * 64];
__device__ float g_tmp_e[N_EDGES * 64];
__device__ double g_stats[16];   // zero-initialized; finalize re-zeroes after use
__device__ float g_mr[16];       // (mean, rstd) pairs

// Static device-side pointer table: resolved at module load, no host API needed.
#define B_XN 0
#define B_XN_OLD 1
#define B_TMP_N 2
#define B_SI 3
#define B_SJ 4
#define B_XE 5
#define B_XE_OLD 6
#define B_TMP_E 7
__device__ float* const g_tab[8] = {g_xn, g_xn_old, g_tmp_n, g_si,
                                    g_sj, g_xe, g_xe_old, g_tmp_e};

// ---------------- packed f32x2 helpers -----------------------------------------
__device__ __forceinline__ unsigned long long pack2(float f) {
    unsigned long long r;
    asm("mov.b64 %0, {%1, %1};" : "=l"(r) : "f"(f));
    return r;
}
__device__ __forceinline__ void fma2(unsigned long long& d, unsigned long long a,
                                     unsigned long long b) {
    asm("fma.rn.f32x2 %0, %1, %2, %0;" : "+l"(d) : "l"(a), "l"(b));
}
__device__ __forceinline__ float2 unpack2(unsigned long long v) {
    float2 r;
    asm("mov.b64 {%0, %1}, %2;" : "=f"(r.x), "=f"(r.y) : "l"(v));
    return r;
}
__device__ __forceinline__ float f4get(const float4& v, int k) {
    return k == 0 ? v.x : (k == 1 ? v.y : (k == 2 ? v.z : v.w));
}

// 64-output accumulation: acc[32] packed pairs, weight row = 64 floats
__device__ __forceinline__ void doRow32(unsigned long long* acc, const ulonglong2* row,
                                        unsigned long long f2) {
#pragma unroll
    for (int q = 0; q < 16; q++) {
        ulonglong2 kk = row[q];
        fma2(acc[2 * q + 0], f2, kk.x);
        fma2(acc[2 * q + 1], f2, kk.y);
    }
}

// ---------------- block-level stat reduction -> double atomics ------------------
// scr: >=32 floats of scratch in DYNAMIC shared memory (reused weight buffer).
// A __syncthreads() before first write makes the reuse safe (all threads have
// finished reading the weights by then). No static shared => the 48KB kernels
// stay exactly at the 49152-byte dynamic limit.
__device__ __forceinline__ void block_stats(float s, float q, int slot, float* scr) {
#pragma unroll
    for (int o = 16; o > 0; o >>= 1) {
        s += __shfl_down_sync(0xFFFFFFFFu, s, o);
        q += __shfl_down_sync(0xFFFFFFFFu, q, o);
    }
    int wid = threadIdx.x >> 5, lid = threadIdx.x & 31;
    int nw = (blockDim.x + 31) >> 5;
    __syncthreads();  // weights no longer needed; safe to reuse buffer
    if (lid == 0) { scr[wid] = s; scr[16 + wid] = q; }
    __syncthreads();
    if (threadIdx.x == 0) {
        float S = 0.f, Q = 0.f;
        for (int w = 0; w < nw; w++) { S += scr[w]; Q += scr[16 + w]; }
        atomicAdd(&g_stats[slot * 2 + 0], (double)S);
        atomicAdd(&g_stats[slot * 2 + 1], (double)Q);
    }
}

// ---------------- kernels -------------------------------------------------------

__global__ void k_zero(int bufid, unsigned int n4) {
    unsigned int t = blockIdx.x * blockDim.x + threadIdx.x;
    if (t < n4) reinterpret_cast<float4*>(g_tab[bufid])[t] = make_float4(0.f, 0.f, 0.f, 0.f);
}

// First conv of a double-layer: channel-major input x[CIN][P] -> out[P][64], + stats.
template <int CIN>
__global__ void k_convA(const float* __restrict__ x, const float* __restrict__ K,
                        int outid, int P, int slot) {
    extern __shared__ float sKs[];  // [CIN][64] transposed
    float* __restrict__ out = g_tab[outid];
    for (int t = threadIdx.x; t < CIN * 64; t += blockDim.x) {
        int c = t >> 6, o = t & 63;
        sKs[t] = K[o * CIN + c];
    }
    __syncthreads();
    int p = blockIdx.x * blockDim.x + threadIdx.x;
    float lsum = 0.f, lsq = 0.f;
    if (p < P) {
        unsigned long long acc[32];
#pragma unroll
        for (int q = 0; q < 32; q++) acc[q] = 0ull;
        const ulonglong2* Kp = reinterpret_cast<const ulonglong2*>(sKs);
#pragma unroll 2
        for (int c = 0; c < CIN; c++) {
            unsigned long long f2 = pack2(x[(size_t)c * P + p]);
            doRow32(acc, Kp + (size_t)c * 16, f2);
        }
        float4* o4 = reinterpret_cast<float4*>(out + (size_t)p * 64);
#pragma unroll
        for (int q = 0; q < 16; q++) {
            float2 v0 = unpack2(acc[2 * q]), v1 = unpack2(acc[2 * q + 1]);
            float4 w = make_float4(v0.x, v0.y, v1.x, v1.y);
            o4[q] = w;
            lsum += w.x + w.y + w.z + w.w;
            lsq += w.x * w.x + w.y * w.y + w.z * w.z + w.w * w.w;
        }
    }
    block_stats(lsum, lsq, slot, sKs);
}

// Second conv: LN(mean/rstd from mrslot)+ReLU on in[P][64], then K[64][64] -> out[P][64].
// out2id >= 0: also write a copy (anchor). STATS: accumulate output stats for outer LN.
template <bool STATS>
__global__ void k_convB(int inid, const float* __restrict__ K, int outid, int out2id,
                        int P, int mrslot, int statslot) {
    extern __shared__ float sKs[];  // [64][64] transposed
    const float* __restrict__ in = g_tab[inid];
    float* __restrict__ out = g_tab[outid];
    float* __restrict__ out2 = out2id >= 0 ? g_tab[out2id] : nullptr;
    for (int t = threadIdx.x; t < 64 * 64; t += blockDim.x) {
        int c = t >> 6, o = t & 63;
        sKs[t] = K[o * 64 + c];
    }
    __syncthreads();
    float m = g_mr[mrslot * 2 + 0], r = g_mr[mrslot * 2 + 1];
    int p = blockIdx.x * blockDim.x + threadIdx.x;
    float lsum = 0.f, lsq = 0.f;
    if (p < P) {
        const float4* i4 = reinterpret_cast<const float4*>(in + (size_t)p * 64);
        unsigned long long acc[32];
#pragma unroll
        for (int q = 0; q < 32; q++) acc[q] = 0ull;
        const ulonglong2* Kp = reinterpret_cast<const ulonglong2*>(sKs);
#pragma unroll 2
        for (int c4 = 0; c4 < 16; c4++) {
            float4 v = i4[c4];
#pragma unroll
            for (int k = 0; k < 4; k++) {
                int c = c4 * 4 + k;
                float t0 = (f4get(v, k) - m) * r;
                t0 = t0 > 0.f ? t0 : 0.f;
                doRow32(acc, Kp + (size_t)c * 16, pack2(t0));
            }
        }
        float4* o4 = reinterpret_cast<float4*>(out + (size_t)p * 64);
        float4* o4b = out2 ? reinterpret_cast<float4*>(out2 + (size_t)p * 64) : nullptr;
#pragma unroll
        for (int q = 0; q < 16; q++) {
            float2 v0 = unpack2(acc[2 * q]), v1 = unpack2(acc[2 * q + 1]);
            float4 w = make_float4(v0.x, v0.y, v1.x, v1.y);
            o4[q] = w;
            if (o4b) o4b[q] = w;
            if (STATS) {
                lsum += w.x + w.y + w.z + w.w;
                lsq += w.x * w.x + w.y * w.y + w.z * w.z + w.w * w.w;
            }
        }
    }
    if (STATS) block_stats(lsum, lsq, statslot, sKs);
}

__global__ void k_finalize(int slot, double count) {
    double s = g_stats[slot * 2 + 0], q = g_stats[slot * 2 + 1];
    double m = s / count;
    double var = q / count - m * m;
    g_mr[slot * 2 + 0] = (float)m;
    g_mr[slot * 2 + 1] = rsqrtf((float)var + LN_EPS);
    g_stats[slot * 2 + 0] = 0.0;  // restore zero for next graph replay
    g_stats[slot * 2 + 1] = 0.0;
}

// Fused edge feature build (gather + [intX, xe, gradX] concat) + KE1 conv. Out + stats.
// Dynamic smem = 49152 B exactly (the default cap); NO static shared in this kernel.
__global__ void k_edgeA(const int* __restrict__ iInd, const int* __restrict__ jInd,
                        const float* __restrict__ K,  // [64][192]
                        int outid, int slot) {
    extern __shared__ float sKs[];  // [192][64] transposed
    const float* __restrict__ xn = g_tab[B_XN];
    const float* __restrict__ xe = g_tab[B_XE];
    float* __restrict__ out = g_tab[outid];
    for (int t = threadIdx.x; t < 192 * 64; t += blockDim.x) {
        int c = t >> 6, o = t & 63;
        sKs[t] = K[o * 192 + c];
    }
    __syncthreads();
    int e = blockIdx.x * blockDim.x + threadIdx.x;
    float lsum = 0.f, lsq = 0.f;
    if (e < N_EDGES) {
        int i = iInd[e], j = jInd[e];
        const float4* xi4 = reinterpret_cast<const float4*>(xn + (size_t)i * 64);
        const float4* xj4 = reinterpret_cast<const float4*>(xn + (size_t)j * 64);
        const float4* xv4 = reinterpret_cast<const float4*>(xe + (size_t)e * 64);
        unsigned long long acc[32];
#pragma unroll
        for (int q = 0; q < 32; q++) acc[q] = 0ull;
        const ulonglong2* Kp = reinterpret_cast<const ulonglong2*>(sKs);
#pragma unroll 1
        for (int c4 = 0; c4 < 16; c4++) {
            float4 a = xi4[c4], b = xj4[c4], x = xv4[c4];
#pragma unroll
            for (int k = 0; k < 4; k++) {
                int c = c4 * 4 + k;
                float fa = f4get(a, k), fb = f4get(b, k), fx = f4get(x, k);
                doRow32(acc, Kp + (size_t)c * 16, pack2((fa + fb) * 0.5f));     // intX
                doRow32(acc, Kp + (size_t)(64 + c) * 16, pack2(fx));            // xe
                doRow32(acc, Kp + (size_t)(128 + c) * 16, pack2(fa - fb));      // gradX
            }
        }
        float4* o4 = reinterpret_cast<float4*>(out + (size_t)e * 64);
#pragma unroll
        for (int q = 0; q < 16; q++) {
            float2 v0 = unpack2(acc[2 * q]), v1 = unpack2(acc[2 * q + 1]);
            float4 w = make_float4(v0.x, v0.y, v1.x, v1.y);
            o4[q] = w;
            lsum += w.x + w.y + w.z + w.w;
            lsq += w.x * w.x + w.y * w.y + w.z * w.z + w.w * w.w;
        }
    }
    block_stats(lsum, lsq, slot, sKs);
}

// Fused node feature build ([aveE, divE, xn]) + KN1 conv. Out + stats. No static shared.
__global__ void k_nodeA(const float* __restrict__ K,  // [64][192]
                        int outid, int slot) {
    extern __shared__ float sKs[];
    const float* __restrict__ si = g_tab[B_SI];
    const float* __restrict__ sj = g_tab[B_SJ];
    const float* __restrict__ xn = g_tab[B_XN];
    float* __restrict__ out = g_tab[outid];
    for (int t = threadIdx.x; t < 192 * 64; t += blockDim.x) {
        int c = t >> 6, o = t & 63;
        sKs[t] = K[o * 192 + c];
    }
    __syncthreads();
    int p = blockIdx.x * blockDim.x + threadIdx.x;
    float lsum = 0.f, lsq = 0.f;
    if (p < N_NODES) {
        const float4* a4 = reinterpret_cast<const float4*>(si + (size_t)p * 64);
        const float4* b4 = reinterpret_cast<const float4*>(sj + (size_t)p * 64);
        const float4* x4 = reinterpret_cast<const float4*>(xn + (size_t)p * 64);
        unsigned long long acc[32];
#pragma unroll
        for (int q = 0; q < 32; q++) acc[q] = 0ull;
        const ulonglong2* Kp = reinterpret_cast<const ulonglong2*>(sKs);
#pragma unroll 1
        for (int c4 = 0; c4 < 16; c4++) {
            float4 a = a4[c4], b = b4[c4], x = x4[c4];
#pragma unroll
            for (int k = 0; k < 4; k++) {
                int c = c4 * 4 + k;
                float fa = f4get(a, k), fb = f4get(b, k), fx = f4get(x, k);
                doRow32(acc, Kp + (size_t)c * 16, pack2((fa + fb) * 0.5f));     // aveE
                doRow32(acc, Kp + (size_t)(64 + c) * 16, pack2(fa - fb));       // divE
                doRow32(acc, Kp + (size_t)(128 + c) * 16, pack2(fx));           // xn
            }
        }
        float4* o4 = reinterpret_cast<float4*>(out + (size_t)p * 64);
#pragma unroll
        for (int q = 0; q < 16; q++) {
            float2 v0 = unpack2(acc[2 * q]), v1 = unpack2(acc[2 * q + 1]);
            float4 w = make_float4(v0.x, v0.y, v1.x, v1.y);
            o4[q] = w;
            lsum += w.x + w.y + w.z + w.w;
            lsq += w.x * w.x + w.y * w.y + w.z * w.z + w.w * w.w;
        }
    }
    block_stats(lsum, lsq, slot, sKs);
}

// Scatter xe rows into per-node sums at i (si) and j (sj) via vector red.
__global__ void k_scatter(const int* __restrict__ iInd, const int* __restrict__ jInd) {
    const float* __restrict__ xe = g_tab[B_XE];
    float* __restrict__ si = g_tab[B_SI];
    float* __restrict__ sj = g_tab[B_SJ];
    unsigned int t = blockIdx.x * blockDim.x + threadIdx.x;
    if (t >= (unsigned int)N_EDGES * 16u) return;
    int e = t >> 4, q = t & 15;
    float4 v = reinterpret_cast<const float4*>(xe)[(size_t)e * 16 + q];
    int i = __ldg(&iInd[e]), j = __ldg(&jInd[e]);
    float* pi = si + (size_t)i * 64 + q * 4;
    float* pj = sj + (size_t)j * 64 + q * 4;
    asm volatile("red.global.add.v4.f32 [%0], {%1,%2,%3,%4};" ::"l"(pi), "f"(v.x),
                 "f"(v.y), "f"(v.z), "f"(v.w)
                 : "memory");
    asm volatile("red.global.add.v4.f32 [%0], {%1,%2,%3,%4};" ::"l"(pj), "f"(v.x),
                 "f"(v.y), "f"(v.z), "f"(v.w)
                 : "memory");
}

// xe = 2*xe - xe_old + H2 * LN(dxe)
__global__ void k_update_edge(int mrslot) {
    float* __restrict__ xe = g_tab[B_XE];
    const float* __restrict__ xe_old = g_tab[B_XE_OLD];
    const float* __restrict__ dxe = g_tab[B_TMP_E];
    unsigned int t = blockIdx.x * blockDim.x + threadIdx.x;
    if (t >= (unsigned int)N_EDGES * 16u) return;
    float m = g_mr[mrslot * 2 + 0], r = g_mr[mrslot * 2 + 1];
    float4 x = reinterpret_cast<float4*>(xe)[t];
    float4 o = reinterpret_cast<const float4*>(xe_old)[t];
    float4 d = reinterpret_cast<const float4*>(dxe)[t];
    float4 w;
    w.x = 2.f * x.x - o.x + H2f * ((d.x - m) * r);
    w.y = 2.f * x.y - o.y + H2f * ((d.y - m) * r);
    w.z = 2.f * x.z - o.z + H2f * ((d.z - m) * r);
    w.w = 2.f * x.w - o.w + H2f * ((d.w - m) * r);
    reinterpret_cast<float4*>(xe)[t] = w;
}

// xn = 2*xn - xn_old + H2 * dxn
__global__ void k_update_node() {
    float* __restrict__ xn = g_tab[B_XN];
    const float* __restrict__ xn_old = g_tab[B_XN_OLD];
    const float* __restrict__ dxn = g_tab[B_TMP_N];
    unsigned int t = blockIdx.x * blockDim.x + threadIdx.x;
    if (t >= (unsigned int)N_NODES * 16u) return;
    float4 x = reinterpret_cast<float4*>(xn)[t];
    float4 o = reinterpret_cast<const float4*>(xn_old)[t];
    float4 d = reinterpret_cast<const float4*>(dxn)[t];
    float4 w;
    w.x = 2.f * x.x - o.x + H2f * d.x;
    w.y = 2.f * x.y - o.y + H2f * d.y;
    w.z = 2.f * x.z - o.z + H2f * d.z;
    w.w = 2.f * x.w - o.w + H2f * d.w;
    reinterpret_cast<float4*>(xn)[t] = w;
}

// Final close conv: out[o][p] = sum_c KNclose[o][c] * xn[p][c]  (channel-major output)
__global__ void k_close(const float* __restrict__ K, float* __restrict__ out) {
    __shared__ float sKs[64 * 32];  // [c][32] transposed (8KB static, well under limit)
    const float* __restrict__ xn = g_tab[B_XN];
    for (int t = threadIdx.x; t < 64 * 32; t += blockDim.x) {
        int c = t >> 5, o = t & 31;
        sKs[t] = K[o * 64 + c];
    }
    __syncthreads();
    int p = blockIdx.x * blockDim.x + threadIdx.x;
    if (p >= N_NODES) return;
    const float4* x4 = reinterpret_cast<const float4*>(xn + (size_t)p * 64);
    unsigned long long acc[16];
#pragma unroll
    for (int q = 0; q < 16; q++) acc[q] = 0ull;
#pragma unroll 2
    for (int c4 = 0; c4 < 16; c4++) {
        float4 v = x4[c4];
#pragma unroll
        for (int k = 0; k < 4; k++) {
            int c = c4 * 4 + k;
            unsigned long long f2 = pack2(f4get(v, k));
            const ulonglong2* row = reinterpret_cast<const ulonglong2*>(sKs + c * 32);
#pragma unroll
            for (int q = 0; q < 8; q++) {
                ulonglong2 kk = row[q];
                fma2(acc[2 * q + 0], f2, kk.x);
                fma2(acc[2 * q + 1], f2, kk.y);
            }
        }
    }
#pragma unroll
    for (int q = 0; q < 8; q++) {
        float2 v0 = unpack2(acc[2 * q]), v1 = unpack2(acc[2 * q + 1]);
        out[(size_t)(4 * q + 0) * N_NODES + p] = v0.x;
        out[(size_t)(4 * q + 1) * N_NODES + p] = v0.y;
        out[(size_t)(4 * q + 2) * N_NODES + p] = v1.x;
        out[(size_t)(4 * q + 3) * N_NODES + p] = v1.y;
    }
}

// Transpose xe [E][64] -> out [64][E] (tiled)
__global__ void k_xe_out(float* __restrict__ out) {
    __shared__ float tile[32][33];
    const float* __restrict__ xe = g_tab[B_XE];
    int e0 = blockIdx.x * 32;
    int c0 = blockIdx.y * 32;
    int tx = threadIdx.x, ty = threadIdx.y;
    tile[ty][tx] = xe[(size_t)(e0 + ty) * 64 + c0 + tx];
    __syncthreads();
    out[(size_t)(c0 + ty) * N_EDGES + e0 + tx] = tile[tx][ty];
}

// ---------------- launch --------------------------------------------------------
extern "C" void kernel_launch(void* const* d_in, const int* in_sizes, int n_in,
                              void* d_out, int out_size) {
    const float* xn_in = (const float*)d_in[0];
    const float* xe_in = (const float*)d_in[1];
    const int* iInd = (const int*)d_in[2];
    const int* jInd = (const int*)d_in[3];
    const float* K1N = (const float*)d_in[4];
    const float* K2N = (const float*)d_in[5];
    const float* K1E = (const float*)d_in[6];
    const float* K2E = (const float*)d_in[7];
    const float* KNc = (const float*)d_in[8];
    const float* KE1 = (const float*)d_in[9];
    const float* KE2 = (const float*)d_in[10];
    const float* KN1 = (const float*)d_in[11];
    const float* KN2 = (const float*)d_in[12];
    float* out = (float*)d_out;

    const int T = 256;
    const int gN = (N_NODES + T - 1) / T;
    const int gE = (N_EDGES + T - 1) / T;
    const size_t sh16 = 16 * 64 * sizeof(float);
    const size_t sh64 = 64 * 64 * sizeof(float);
    const size_t sh192 = 192 * 64 * sizeof(float);  // 49152 B == default cap, 0 static
    const double CNT_N = 64.0 * N_NODES, CNT_E = 64.0 * N_EDGES;
    const unsigned int n4N = (unsigned int)N_NODES * 16u;

    // ---- open nodes: conv -> global LN -> relu -> conv ; anchor copy to xn_old
    k_convA<16><<<gN, T, sh16>>>(xn_in, K1N, B_TMP_N, N_NODES, 0);
    k_finalize<<<1, 1>>>(0, CNT_N);
    k_convB<false><<<gN, T, sh64>>>(B_TMP_N, K2N, B_XN, B_XN_OLD, N_NODES, 0, 0);

    // ---- open edges
    k_convA<16><<<gE, T, sh16>>>(xe_in, K1E, B_TMP_E, N_EDGES, 1);
    k_finalize<<<1, 1>>>(1, CNT_E);
    k_convB<false><<<gE, T, sh64>>>(B_TMP_E, K2E, B_XE, B_XE_OLD, N_EDGES, 1, 1);

    for (int l = 0; l < 2; l++) {
        // node-side scatter sums from current xe (before updates)
        k_zero<<<(n4N + T - 1) / T, T>>>(B_SI, n4N);
        k_zero<<<(n4N + T - 1) / T, T>>>(B_SJ, n4N);
        k_scatter<<<(N_EDGES * 16) / T, T>>>(iInd, jInd);

        // edge path: gather+concat+KE1 -> LN stats -> LN+relu+KE2 (+stats for outer LN)
        k_edgeA<<<gE, T, sh192>>>(iInd, jInd, KE1 + (size_t)l * 64 * 192, B_TMP_E, 2);
        k_finalize<<<1, 1>>>(2, CNT_E);
        k_convB<true><<<gE, T, sh64>>>(B_TMP_E, KE2 + (size_t)l * 64 * 64, B_TMP_E, -1,
                                       N_EDGES, 2, 3);
        k_finalize<<<1, 1>>>(3, CNT_E);

        // node path: [aveE, divE, xn]+KN1 -> LN stats -> LN+relu+KN2 (no outer LN)
        k_nodeA<<<gN, T, sh192>>>(KN1 + (size_t)l * 64 * 192, B_TMP_N, 4);
        k_finalize<<<1, 1>>>(4, CNT_N);
        k_convB<false><<<gN, T, sh64>>>(B_TMP_N, KN2 + (size_t)l * 64 * 64, B_TMP_N, -1,
                                        N_NODES, 4, 0);

        // leapfrog updates (after both paths consumed pre-update xn/xe)
        k_update_node<<<(N_NODES * 16 + T - 1) / T, T>>>();
        k_update_edge<<<(N_EDGES * 16) / T, T>>>(3);
    }

    // outputs: xn -> KNclose (channel-major), then xe transposed to channel-major
    k_close<<<gN, T>>>(KNc, out);
    dim3 tb(32, 32), tg(N_EDGES / 32, 2);
    k_xe_out<<<tg, tb>>>(out + (size_t)32 * N_NODES);
}

// round 6
// speedup vs baseline: 1.0176x; 1.0176x over previous
#include <cuda_runtime.h>
#include <cstdint>

#define N_NODES 40000
#define N_EDGES 400000
#define H2f 0.01f
#define LN_EPS 1e-5f

// ---------------- device scratch (allocation-free rule: __device__ globals) ----
__device__ float g_xn[N_NODES * 64];
__device__ float g_xn_old[N_NODES * 64];
__device__ float g_tmp_n[N_NODES * 64];
__device__ float g_si[N_NODES * 64];
__device__ float g_sj[N_NODES * 64];
__device__ float g_xe[N_EDGES * 64];
__device__ float g_xe_old[N_EDGES * 64];
__device__ float g_tmp_e[N_EDGES * 64];
__device__ double g_stats[16];   // zero-initialized; finalize re-zeroes after use
__device__ float g_mr[16];       // (mean, rstd) pairs

// Static device-side pointer table: resolved at module load, no host API needed.
#define B_XN 0
#define B_XN_OLD 1
#define B_TMP_N 2
#define B_SI 3
#define B_SJ 4
#define B_XE 5
#define B_XE_OLD 6
#define B_TMP_E 7
__device__ float* const g_tab[8] = {g_xn, g_xn_old, g_tmp_n, g_si,
                                    g_sj, g_xe, g_xe_old, g_tmp_e};

typedef unsigned long long u64;

// ---------------- packed f32x2 helpers -----------------------------------------
__device__ __forceinline__ u64 pack2(float f) {
    u64 r;
    asm("mov.b64 %0, {%1, %1};" : "=l"(r) : "f"(f));
    return r;
}
__device__ __forceinline__ void fma2(u64& d, u64 a, u64 b) {
    asm("fma.rn.f32x2 %0, %1, %2, %0;" : "+l"(d) : "l"(a), "l"(b));
}
__device__ __forceinline__ float2 unpack2(u64 v) {
    float2 r;
    asm("mov.b64 {%0, %1}, %2;" : "=f"(r.x), "=f"(r.y) : "l"(v));
    return r;
}
__device__ __forceinline__ float f4get(const float4& v, int k) {
    return k == 0 ? v.x : (k == 1 ? v.y : (k == 2 ? v.z : v.w));
}

// Inner: one input channel, 2 positions (f0/f1 broadcast-packed), 32 outputs.
// row = 8 x ulonglong2 (32 outputs as 16 packed pairs). 8 LDS.128 feed 32 FFMA2.
__device__ __forceinline__ void doHalf(u64* acc0, u64* acc1, const ulonglong2* row,
                                       u64 f0, u64 f1) {
#pragma unroll
    for (int q = 0; q < 8; q++) {
        ulonglong2 kk = row[q];
        fma2(acc0[2 * q + 0], f0, kk.x);
        fma2(acc0[2 * q + 1], f0, kk.y);
        fma2(acc1[2 * q + 0], f1, kk.x);
        fma2(acc1[2 * q + 1], f1, kk.y);
    }
}

// Store 32 outputs (16 packed pairs) for one position + accumulate stats.
__device__ __forceinline__ void storeAcc(float* dst, const u64* acc, float& lsum,
                                         float& lsq) {
    float4* d4 = reinterpret_cast<float4*>(dst);
#pragma unroll
    for (int q = 0; q < 8; q++) {
        float2 v0 = unpack2(acc[2 * q]), v1 = unpack2(acc[2 * q + 1]);
        float4 w = make_float4(v0.x, v0.y, v1.x, v1.y);
        d4[q] = w;
        lsum += w.x + w.y + w.z + w.w;
        lsq += w.x * w.x + w.y * w.y + w.z * w.z + w.w * w.w;
    }
}

// ---------------- block-level stat reduction -> double atomics ------------------
// scr: >=32 floats of DYNAMIC shared scratch (reused weight buffer; synced).
__device__ __forceinline__ void block_stats(float s, float q, int slot, float* scr) {
#pragma unroll
    for (int o = 16; o > 0; o >>= 1) {
        s += __shfl_down_sync(0xFFFFFFFFu, s, o);
        q += __shfl_down_sync(0xFFFFFFFFu, q, o);
    }
    int wid = threadIdx.x >> 5, lid = threadIdx.x & 31;
    int nw = (blockDim.x + 31) >> 5;
    __syncthreads();  // weights no longer needed; safe to reuse buffer
    if (lid == 0) { scr[wid] = s; scr[16 + wid] = q; }
    __syncthreads();
    if (threadIdx.x == 0) {
        float S = 0.f, Q = 0.f;
        for (int w = 0; w < nw; w++) { S += scr[w]; Q += scr[16 + w]; }
        atomicAdd(&g_stats[slot * 2 + 0], (double)S);
        atomicAdd(&g_stats[slot * 2 + 1], (double)Q);
    }
}

// ---------------- kernels -------------------------------------------------------

__global__ void k_zero2(unsigned int n4) {  // zero si and sj together
    unsigned int t = blockIdx.x * blockDim.x + threadIdx.x;
    float4 z = make_float4(0.f, 0.f, 0.f, 0.f);
    if (t < n4) {
        reinterpret_cast<float4*>(g_tab[B_SI])[t] = z;
        reinterpret_cast<float4*>(g_tab[B_SJ])[t] = z;
    }
}

// First conv of a double-layer: channel-major input x[CIN][P] -> out[P][64], + stats.
// Thread layout: pair = tid>>1 (2 consecutive positions), h = tid&1 (32 outputs).
template <int CIN>
__global__ void __launch_bounds__(256) k_convA(const float* __restrict__ x,
                                               const float* __restrict__ K, int outid,
                                               int P, int slot) {
    extern __shared__ float sKs[];  // [CIN][64] transposed
    float* __restrict__ out = g_tab[outid];
    for (int t = threadIdx.x; t < CIN * 64; t += blockDim.x) {
        int c = t >> 6, o = t & 63;
        sKs[t] = K[o * CIN + c];
    }
    __syncthreads();
    int pair = blockIdx.x * (blockDim.x >> 1) + (threadIdx.x >> 1);
    int h = threadIdx.x & 1;
    int p0 = 2 * pair;
    float lsum = 0.f, lsq = 0.f;
    if (p0 < P) {
        u64 acc0[16], acc1[16];
#pragma unroll
        for (int q = 0; q < 16; q++) { acc0[q] = 0ull; acc1[q] = 0ull; }
        const ulonglong2* Kp = reinterpret_cast<const ulonglong2*>(sKs);
#pragma unroll 2
        for (int c = 0; c < CIN; c++) {
            float2 xv = *reinterpret_cast<const float2*>(x + (size_t)c * P + p0);
            doHalf(acc0, acc1, Kp + c * 16 + h * 8, pack2(xv.x), pack2(xv.y));
        }
        storeAcc(out + (size_t)p0 * 64 + h * 32, acc0, lsum, lsq);
        storeAcc(out + (size_t)(p0 + 1) * 64 + h * 32, acc1, lsum, lsq);
    }
    block_stats(lsum, lsq, slot, sKs);
}

// Second conv: LN+ReLU on in[P][64], then K[64][64] -> out[P][64].
template <bool STATS>
__global__ void __launch_bounds__(256) k_convB(int inid, const float* __restrict__ K,
                                               int outid, int out2id, int P, int mrslot,
                                               int statslot) {
    extern __shared__ float sKs[];  // [64][64] transposed
    const float* __restrict__ in = g_tab[inid];
    float* __restrict__ out = g_tab[outid];
    float* __restrict__ out2 = out2id >= 0 ? g_tab[out2id] : nullptr;
    for (int t = threadIdx.x; t < 64 * 64; t += blockDim.x) {
        int c = t >> 6, o = t & 63;
        sKs[t] = K[o * 64 + c];
    }
    __syncthreads();
    float m = g_mr[mrslot * 2 + 0], r = g_mr[mrslot * 2 + 1];
    int pair = blockIdx.x * (blockDim.x >> 1) + (threadIdx.x >> 1);
    int h = threadIdx.x & 1;
    int p0 = 2 * pair;
    float lsum = 0.f, lsq = 0.f;
    if (p0 < P) {
        const float4* i40 = reinterpret_cast<const float4*>(in + (size_t)p0 * 64);
        const float4* i41 = reinterpret_cast<const float4*>(in + (size_t)(p0 + 1) * 64);
        u64 acc0[16], acc1[16];
#pragma unroll
        for (int q = 0; q < 16; q++) { acc0[q] = 0ull; acc1[q] = 0ull; }
        const ulonglong2* Kp = reinterpret_cast<const ulonglong2*>(sKs);
#pragma unroll 2
        for (int c4 = 0; c4 < 16; c4++) {
            float4 v0 = i40[c4], v1 = i41[c4];
#pragma unroll
            for (int k = 0; k < 4; k++) {
                int c = c4 * 4 + k;
                float t0 = (f4get(v0, k) - m) * r;
                t0 = t0 > 0.f ? t0 : 0.f;
                float t1 = (f4get(v1, k) - m) * r;
                t1 = t1 > 0.f ? t1 : 0.f;
                doHalf(acc0, acc1, Kp + c * 16 + h * 8, pack2(t0), pack2(t1));
            }
        }
        storeAcc(out + (size_t)p0 * 64 + h * 32, acc0, lsum, lsq);
        storeAcc(out + (size_t)(p0 + 1) * 64 + h * 32, acc1, lsum, lsq);
        if (out2) {
            float4* a = reinterpret_cast<float4*>(out2 + (size_t)p0 * 64 + h * 32);
            float4* b = reinterpret_cast<float4*>(out2 + (size_t)(p0 + 1) * 64 + h * 32);
#pragma unroll
            for (int q = 0; q < 8; q++) {
                float2 v0 = unpack2(acc0[2 * q]), w0 = unpack2(acc0[2 * q + 1]);
                a[q] = make_float4(v0.x, v0.y, w0.x, w0.y);
                float2 v1 = unpack2(acc1[2 * q]), w1 = unpack2(acc1[2 * q + 1]);
                b[q] = make_float4(v1.x, v1.y, w1.x, w1.y);
            }
        }
    }
    if (STATS) block_stats(lsum, lsq, statslot, sKs);
}

__global__ void k_finalize(int slot, double count) {
    double s = g_stats[slot * 2 + 0], q = g_stats[slot * 2 + 1];
    double m = s / count;
    double var = q / count - m * m;
    g_mr[slot * 2 + 0] = (float)m;
    g_mr[slot * 2 + 1] = rsqrtf((float)var + LN_EPS);
    g_stats[slot * 2 + 0] = 0.0;  // restore zero for next graph replay
    g_stats[slot * 2 + 1] = 0.0;
}

// Fused edge feature build (gather + [intX, xe, gradX]) + KE1 conv. 49152B dyn smem.
__global__ void __launch_bounds__(256) k_edgeA(const int* __restrict__ iInd,
                                               const int* __restrict__ jInd,
                                               const float* __restrict__ K,  // [64][192]
                                               int outid, int slot) {
    extern __shared__ float sKs[];  // [192][64] transposed
    const float* __restrict__ xn = g_tab[B_XN];
    const float* __restrict__ xe = g_tab[B_XE];
    float* __restrict__ out = g_tab[outid];
    for (int t = threadIdx.x; t < 192 * 64; t += blockDim.x) {
        int c = t >> 6, o = t & 63;
        sKs[t] = K[o * 192 + c];
    }
    __syncthreads();
    int pair = blockIdx.x * (blockDim.x >> 1) + (threadIdx.x >> 1);
    int h = threadIdx.x & 1;
    int e0 = 2 * pair;
    float lsum = 0.f, lsq = 0.f;
    if (e0 < N_EDGES) {
        int i0 = iInd[e0], j0 = jInd[e0];
        int i1 = iInd[e0 + 1], j1 = jInd[e0 + 1];
        const float4* xi0 = reinterpret_cast<const float4*>(xn + (size_t)i0 * 64);
        const float4* xj0 = reinterpret_cast<const float4*>(xn + (size_t)j0 * 64);
        const float4* xv0 = reinterpret_cast<const float4*>(xe + (size_t)e0 * 64);
        const float4* xi1 = reinterpret_cast<const float4*>(xn + (size_t)i1 * 64);
        const float4* xj1 = reinterpret_cast<const float4*>(xn + (size_t)j1 * 64);
        const float4* xv1 = reinterpret_cast<const float4*>(xe + (size_t)(e0 + 1) * 64);
        u64 acc0[16], acc1[16];
#pragma unroll
        for (int q = 0; q < 16; q++) { acc0[q] = 0ull; acc1[q] = 0ull; }
        const ulonglong2* Kp = reinterpret_cast<const ulonglong2*>(sKs);
#pragma unroll 1
        for (int c4 = 0; c4 < 16; c4++) {
            float4 a0 = xi0[c4], b0 = xj0[c4], v0 = xv0[c4];
            float4 a1 = xi1[c4], b1 = xj1[c4], v1 = xv1[c4];
#pragma unroll
            for (int k = 0; k < 4; k++) {
                int c = c4 * 4 + k;
                float fa0 = f4get(a0, k), fb0 = f4get(b0, k), fx0 = f4get(v0, k);
                float fa1 = f4get(a1, k), fb1 = f4get(b1, k), fx1 = f4get(v1, k);
                doHalf(acc0, acc1, Kp + c * 16 + h * 8,
                       pack2((fa0 + fb0) * 0.5f), pack2((fa1 + fb1) * 0.5f));  // intX
                doHalf(acc0, acc1, Kp + (64 + c) * 16 + h * 8,
                       pack2(fx0), pack2(fx1));                                // xe
                doHalf(acc0, acc1, Kp + (128 + c) * 16 + h * 8,
                       pack2(fa0 - fb0), pack2(fa1 - fb1));                    // gradX
            }
        }
        storeAcc(out + (size_t)e0 * 64 + h * 32, acc0, lsum, lsq);
        storeAcc(out + (size_t)(e0 + 1) * 64 + h * 32, acc1, lsum, lsq);
    }
    block_stats(lsum, lsq, slot, sKs);
}

// Fused node feature build ([aveE, divE, xn]) + KN1 conv. Out + stats.
__global__ void __launch_bounds__(256) k_nodeA(const float* __restrict__ K,  // [64][192]
                                               int outid, int slot) {
    extern __shared__ float sKs[];
    const float* __restrict__ si = g_tab[B_SI];
    const float* __restrict__ sj = g_tab[B_SJ];
    const float* __restrict__ xn = g_tab[B_XN];
    float* __restrict__ out = g_tab[outid];
    for (int t = threadIdx.x; t < 192 * 64; t += blockDim.x) {
        int c = t >> 6, o = t & 63;
        sKs[t] = K[o * 192 + c];
    }
    __syncthreads();
    int pair = blockIdx.x * (blockDim.x >> 1) + (threadIdx.x >> 1);
    int h = threadIdx.x & 1;
    int p0 = 2 * pair;
    float lsum = 0.f, lsq = 0.f;
    if (p0 < N_NODES) {
        const float4* a40 = reinterpret_cast<const float4*>(si + (size_t)p0 * 64);
        const float4* b40 = reinterpret_cast<const float4*>(sj + (size_t)p0 * 64);
        const float4* x40 = reinterpret_cast<const float4*>(xn + (size_t)p0 * 64);
        const float4* a41 = reinterpret_cast<const float4*>(si + (size_t)(p0 + 1) * 64);
        const float4* b41 = reinterpret_cast<const float4*>(sj + (size_t)(p0 + 1) * 64);
        const float4* x41 = reinterpret_cast<const float4*>(xn + (size_t)(p0 + 1) * 64);
        u64 acc0[16], acc1[16];
#pragma unroll
        for (int q = 0; q < 16; q++) { acc0[q] = 0ull; acc1[q] = 0ull; }
        const ulonglong2* Kp = reinterpret_cast<const ulonglong2*>(sKs);
#pragma unroll 1
        for (int c4 = 0; c4 < 16; c4++) {
            float4 a0 = a40[c4], b0 = b40[c4], v0 = x40[c4];
            float4 a1 = a41[c4], b1 = b41[c4], v1 = x41[c4];
#pragma unroll
            for (int k = 0; k < 4; k++) {
                int c = c4 * 4 + k;
                float fa0 = f4get(a0, k), fb0 = f4get(b0, k), fx0 = f4get(v0, k);
                float fa1 = f4get(a1, k), fb1 = f4get(b1, k), fx1 = f4get(v1, k);
                doHalf(acc0, acc1, Kp + c * 16 + h * 8,
                       pack2((fa0 + fb0) * 0.5f), pack2((fa1 + fb1) * 0.5f));  // aveE
                doHalf(acc0, acc1, Kp + (64 + c) * 16 + h * 8,
                       pack2(fa0 - fb0), pack2(fa1 - fb1));                    // divE
                doHalf(acc0, acc1, Kp + (128 + c) * 16 + h * 8,
                       pack2(fx0), pack2(fx1));                                // xn
            }
        }
        storeAcc(out + (size_t)p0 * 64 + h * 32, acc0, lsum, lsq);
        storeAcc(out + (size_t)(p0 + 1) * 64 + h * 32, acc1, lsum, lsq);
    }
    block_stats(lsum, lsq, slot, sKs);
}

// Scatter xe rows into per-node sums at i (si) and j (sj) via vector red.
__global__ void k_scatter(const int* __restrict__ iInd, const int* __restrict__ jInd) {
    const float* __restrict__ xe = g_tab[B_XE];
    float* __restrict__ si = g_tab[B_SI];
    float* __restrict__ sj = g_tab[B_SJ];
    unsigned int t = blockIdx.x * blockDim.x + threadIdx.x;
    if (t >= (unsigned int)N_EDGES * 16u) return;
    int e = t >> 4, q = t & 15;
    float4 v = reinterpret_cast<const float4*>(xe)[(size_t)e * 16 + q];
    int i = __ldg(&iInd[e]), j = __ldg(&jInd[e]);
    float* pi = si + (size_t)i * 64 + q * 4;
    float* pj = sj + (size_t)j * 64 + q * 4;
    asm volatile("red.global.add.v4.f32 [%0], {%1,%2,%3,%4};" ::"l"(pi), "f"(v.x),
                 "f"(v.y), "f"(v.z), "f"(v.w)
                 : "memory");
    asm volatile("red.global.add.v4.f32 [%0], {%1,%2,%3,%4};" ::"l"(pj), "f"(v.x),
                 "f"(v.y), "f"(v.z), "f"(v.w)
                 : "memory");
}

// xe = 2*xe - xe_old + H2 * LN(dxe)
__global__ void k_update_edge(int mrslot) {
    float* __restrict__ xe = g_tab[B_XE];
    const float* __restrict__ xe_old = g_tab[B_XE_OLD];
    const float* __restrict__ dxe = g_tab[B_TMP_E];
    unsigned int t = blockIdx.x * blockDim.x + threadIdx.x;
    if (t >= (unsigned int)N_EDGES * 16u) return;
    float m = g_mr[mrslot * 2 + 0], r = g_mr[mrslot * 2 + 1];
    float4 x = reinterpret_cast<float4*>(xe)[t];
    float4 o = reinterpret_cast<const float4*>(xe_old)[t];
    float4 d = reinterpret_cast<const float4*>(dxe)[t];
    float4 w;
    w.x = 2.f * x.x - o.x + H2f * ((d.x - m) * r);
    w.y = 2.f * x.y - o.y + H2f * ((d.y - m) * r);
    w.z = 2.f * x.z - o.z + H2f * ((d.z - m) * r);
    w.w = 2.f * x.w - o.w + H2f * ((d.w - m) * r);
    reinterpret_cast<float4*>(xe)[t] = w;
}

// xn = 2*xn - xn_old + H2 * dxn
__global__ void k_update_node() {
    float* __restrict__ xn = g_tab[B_XN];
    const float* __restrict__ xn_old = g_tab[B_XN_OLD];
    const float* __restrict__ dxn = g_tab[B_TMP_N];
    unsigned int t = blockIdx.x * blockDim.x + threadIdx.x;
    if (t >= (unsigned int)N_NODES * 16u) return;
    float4 x = reinterpret_cast<float4*>(xn)[t];
    float4 o = reinterpret_cast<const float4*>(xn_old)[t];
    float4 d = reinterpret_cast<const float4*>(dxn)[t];
    float4 w;
    w.x = 2.f * x.x - o.x + H2f * d.x;
    w.y = 2.f * x.y - o.y + H2f * d.y;
    w.z = 2.f * x.z - o.z + H2f * d.z;
    w.w = 2.f * x.w - o.w + H2f * d.w;
    reinterpret_cast<float4*>(xn)[t] = w;
}

// Final close conv: out[o][p] = sum_c KNclose[o][c] * xn[p][c]  (channel-major output)
__global__ void k_close(const float* __restrict__ K, float* __restrict__ out) {
    __shared__ float sKs[64 * 32];  // [c][32] transposed
    const float* __restrict__ xn = g_tab[B_XN];
    for (int t = threadIdx.x; t < 64 * 32; t += blockDim.x) {
        int c = t >> 5, o = t & 31;
        sKs[t] = K[o * 64 + c];
    }
    __syncthreads();
    int p = blockIdx.x * blockDim.x + threadIdx.x;
    if (p >= N_NODES) return;
    const float4* x4 = reinterpret_cast<const float4*>(xn + (size_t)p * 64);
    u64 acc[16];
#pragma unroll
    for (int q = 0; q < 16; q++) acc[q] = 0ull;
#pragma unroll 2
    for (int c4 = 0; c4 < 16; c4++) {
        float4 v = x4[c4];
#pragma unroll
        for (int k = 0; k < 4; k++) {
            int c = c4 * 4 + k;
            u64 f2 = pack2(f4get(v, k));
            const ulonglong2* row = reinterpret_cast<const ulonglong2*>(sKs + c * 32);
#pragma unroll
            for (int q = 0; q < 8; q++) {
                ulonglong2 kk = row[q];
                fma2(acc[2 * q + 0], f2, kk.x);
                fma2(acc[2 * q + 1], f2, kk.y);
            }
        }
    }
#pragma unroll
    for (int q = 0; q < 8; q++) {
        float2 v0 = unpack2(acc[2 * q]), v1 = unpack2(acc[2 * q + 1]);
        out[(size_t)(4 * q + 0) * N_NODES + p] = v0.x;
        out[(size_t)(4 * q + 1) * N_NODES + p] = v0.y;
        out[(size_t)(4 * q + 2) * N_NODES + p] = v1.x;
        out[(size_t)(4 * q + 3) * N_NODES + p] = v1.y;
    }
}

// Transpose xe [E][64] -> out [64][E] (tiled)
__global__ void k_xe_out(float* __restrict__ out) {
    __shared__ float tile[32][33];
    const float* __restrict__ xe = g_tab[B_XE];
    int e0 = blockIdx.x * 32;
    int c0 = blockIdx.y * 32;
    int tx = threadIdx.x, ty = threadIdx.y;
    tile[ty][tx] = xe[(size_t)(e0 + ty) * 64 + c0 + tx];
    __syncthreads();
    out[(size_t)(c0 + ty) * N_EDGES + e0 + tx] = tile[tx][ty];
}

// ---------------- launch --------------------------------------------------------
extern "C" void kernel_launch(void* const* d_in, const int* in_sizes, int n_in,
                              void* d_out, int out_size) {
    const float* xn_in = (const float*)d_in[0];
    const float* xe_in = (const float*)d_in[1];
    const int* iInd = (const int*)d_in[2];
    const int* jInd = (const int*)d_in[3];
    const float* K1N = (const float*)d_in[4];
    const float* K2N = (const float*)d_in[5];
    const float* K1E = (const float*)d_in[6];
    const float* K2E = (const float*)d_in[7];
    const float* KNc = (const float*)d_in[8];
    const float* KE1 = (const float*)d_in[9];
    const float* KE2 = (const float*)d_in[10];
    const float* KN1 = (const float*)d_in[11];
    const float* KN2 = (const float*)d_in[12];
    float* out = (float*)d_out;

    const int T = 256;
    // 2 positions per thread-pair => threads = positions; pairs per block = T/2
    const int gN = (N_NODES + T - 1) / T;
    const int gE = (N_EDGES + T - 1) / T;
    const size_t sh16 = 16 * 64 * sizeof(float);
    const size_t sh64 = 64 * 64 * sizeof(float);
    const size_t sh192 = 192 * 64 * sizeof(float);  // 49152 B == default cap, 0 static
    const double CNT_N = 64.0 * N_NODES, CNT_E = 64.0 * N_EDGES;
    const unsigned int n4N = (unsigned int)N_NODES * 16u;

    // ---- open nodes: conv -> global LN -> relu -> conv ; anchor copy to xn_old
    k_convA<16><<<gN, T, sh16>>>(xn_in, K1N, B_TMP_N, N_NODES, 0);
    k_finalize<<<1, 1>>>(0, CNT_N);
    k_convB<false><<<gN, T, sh64>>>(B_TMP_N, K2N, B_XN, B_XN_OLD, N_NODES, 0, 0);

    // ---- open edges
    k_convA<16><<<gE, T, sh16>>>(xe_in, K1E, B_TMP_E, N_EDGES, 1);
    k_finalize<<<1, 1>>>(1, CNT_E);
    k_convB<false><<<gE, T, sh64>>>(B_TMP_E, K2E, B_XE, B_XE_OLD, N_EDGES, 1, 1);

    for (int l = 0; l < 2; l++) {
        // node-side scatter sums from current xe (before updates)
        k_zero2<<<(n4N + T - 1) / T, T>>>(n4N);
        k_scatter<<<(N_EDGES * 16) / T, T>>>(iInd, jInd);

        // edge path: gather+concat+KE1 -> LN stats -> LN+relu+KE2 (+stats for outer LN)
        k_edgeA<<<gE, T, sh192>>>(iInd, jInd, KE1 + (size_t)l * 64 * 192, B_TMP_E, 2);
        k_finalize<<<1, 1>>>(2, CNT_E);
        k_convB<true><<<gE, T, sh64>>>(B_TMP_E, KE2 + (size_t)l * 64 * 64, B_TMP_E, -1,
                                       N_EDGES, 2, 3);
        k_finalize<<<1, 1>>>(3, CNT_E);

        // node path: [aveE, divE, xn]+KN1 -> LN stats -> LN+relu+KN2 (no outer LN)
        k_nodeA<<<gN, T, sh192>>>(KN1 + (size_t)l * 64 * 192, B_TMP_N, 4);
        k_finalize<<<1, 1>>>(4, CNT_N);
        k_convB<false><<<gN, T, sh64>>>(B_TMP_N, KN2 + (size_t)l * 64 * 64, B_TMP_N, -1,
                                        N_NODES, 4, 0);

        // leapfrog updates (after both paths consumed pre-update xn/xe)
        k_update_node<<<(N_NODES * 16 + T - 1) / T, T>>>();
        k_update_edge<<<(N_EDGES * 16) / T, T>>>(3);
    }

    // outputs: xn -> KNclose (channel-major), then xe transposed to channel-major
    k_close<<<gN, T>>>(KNc, out);
    dim3 tb(32, 32), tg(N_EDGES / 32, 2);
    k_xe_out<<<tg, tb>>>(out + (size_t)32 * N_NODES);
}